// round 10
// baseline (speedup 1.0000x reference)
#include <cuda_runtime.h>

#define Bb 8
#define Ll 512
#define Dd 256
#define Uu 32
#define TS 16      // s-rows per block in the fused kernel
#define PAD 20     // padded row stride (floats) of weight tile [t][s]
#define RSTRIDE 17 // u64 stride of the reduction buffer (bank-conflict pad)

// scratch: Eq = exp2(C*(q+bh)) and Ek = exp2(C*k), [B*L, U], C = 2*log2(e)
__device__ float g_q[Bb * Ll * Uu];
__device__ float g_k[Bb * Ll * Uu];

__device__ __forceinline__ float fast_ex2(float x) {
    float y; asm("ex2.approx.f32 %0, %1;" : "=f"(y) : "f"(x)); return y;
}
__device__ __forceinline__ float fast_rcp(float x) {
    float y; asm("rcp.approx.f32 %0, %1;" : "=f"(y) : "f"(x)); return y;
}
__device__ __forceinline__ unsigned long long pack2(float lo, float hi) {
    unsigned long long r;
    asm("mov.b64 %0, {%1, %2};" : "=l"(r) : "f"(lo), "f"(hi));
    return r;
}
__device__ __forceinline__ void unpack2(float& lo, float& hi, unsigned long long v) {
    asm("mov.b64 {%0, %1}, %2;" : "=f"(lo), "=f"(hi) : "l"(v));
}
__device__ __forceinline__ void fma2(unsigned long long& d, unsigned long long a,
                                     unsigned long long b) {
    asm("fma.rn.f32x2 %0, %1, %2, %0;" : "+l"(d) : "l"(a), "l"(b));
}
__device__ __forceinline__ void add2(unsigned long long& d, unsigned long long a) {
    asm("add.rn.f32x2 %0, %0, %1;" : "+l"(d) : "l"(a));
}
__device__ __forceinline__ void mul2(unsigned long long& d, unsigned long long a) {
    asm("mul.rn.f32x2 %0, %0, %1;" : "+l"(d) : "l"(a));
}

// ---------------------------------------------------------------------------
// Kernel 1: q/k projections + exp factoring (unchanged, known-good)
// ---------------------------------------------------------------------------
__global__ __launch_bounds__(256) void qk_kernel(const float* __restrict__ x,
                                                 const float* __restrict__ Wt,
                                                 const float* __restrict__ Wx,
                                                 const float* __restrict__ bh) {
    __shared__ float xs[8 * Dd];
    const int row0 = blockIdx.x * 8;

    const float4* xg = (const float4*)(x + (size_t)row0 * Dd);
    float4* xs4 = (float4*)xs;
    xs4[threadIdx.x] = xg[threadIdx.x];
    xs4[threadIdx.x + 256] = xg[threadIdx.x + 256];
    __syncthreads();

    const int u = threadIdx.x & 31;
    const int which = (threadIdx.x >> 5) & 1;
    const int rp = threadIdx.x >> 6;
    const float* __restrict__ W = which ? Wx : Wt;

    float acc0 = which ? 0.f : bh[u];
    float acc1 = acc0;
    const float* xr0 = xs + rp * Dd;
    const float* xr1 = xs + (rp + 4) * Dd;

#pragma unroll 8
    for (int d = 0; d < Dd; d++) {
        float w = W[d * Uu + u];
        acc0 = fmaf(xr0[d], w, acc0);
        acc1 = fmaf(xr1[d], w, acc1);
    }

    const float C2LOG2E = 2.8853900817779268f;  // 2*log2(e)
    float* dst = which ? g_k : g_q;
    dst[(row0 + rp) * Uu + u] = fast_ex2(C2LOG2E * acc0);
    dst[(row0 + rp + 4) * Uu + u] = fast_ex2(C2LOG2E * acc1);
}

// ---------------------------------------------------------------------------
// Phase A (one chunk): thread computes w[t][s] = exp(alpha) for one t and a
// 4-row s-quarter. alpha = sumWa - 2*sum_u Wa_u/(1+Eq*Ek); stored as
// exp2(swl - 2log2e * acc). LDS of q4 is warp-broadcast.
// ---------------------------------------------------------------------------
__device__ __forceinline__ void phaseA(float* __restrict__ sa,
                                       const float* __restrict__ sq,
                                       const float4* __restrict__ swa4,
                                       const float* __restrict__ gkb,
                                       int t, int sq0, float swl) {
    float a0 = 0.f, a1 = 0.f, a2 = 0.f, a3 = 0.f;
    const float4* kg = (const float4*)(gkb + (size_t)t * Uu);
    const float* qb = sq + sq0 * Uu;

#pragma unroll
    for (int i = 0; i < 8; i++) {
        float4 kv = kg[i];
        float4 w4 = swa4[i];
        float4 q0 = *(const float4*)(qb + 4 * i);
        a0 = fmaf(w4.x, fast_rcp(fmaf(kv.x, q0.x, 1.f)), a0);
        a0 = fmaf(w4.y, fast_rcp(fmaf(kv.y, q0.y, 1.f)), a0);
        a0 = fmaf(w4.z, fast_rcp(fmaf(kv.z, q0.z, 1.f)), a0);
        a0 = fmaf(w4.w, fast_rcp(fmaf(kv.w, q0.w, 1.f)), a0);
        float4 q1 = *(const float4*)(qb + Uu + 4 * i);
        a1 = fmaf(w4.x, fast_rcp(fmaf(kv.x, q1.x, 1.f)), a1);
        a1 = fmaf(w4.y, fast_rcp(fmaf(kv.y, q1.y, 1.f)), a1);
        a1 = fmaf(w4.z, fast_rcp(fmaf(kv.z, q1.z, 1.f)), a1);
        a1 = fmaf(w4.w, fast_rcp(fmaf(kv.w, q1.w, 1.f)), a1);
        float4 q2 = *(const float4*)(qb + 2 * Uu + 4 * i);
        a2 = fmaf(w4.x, fast_rcp(fmaf(kv.x, q2.x, 1.f)), a2);
        a2 = fmaf(w4.y, fast_rcp(fmaf(kv.y, q2.y, 1.f)), a2);
        a2 = fmaf(w4.z, fast_rcp(fmaf(kv.z, q2.z, 1.f)), a2);
        a2 = fmaf(w4.w, fast_rcp(fmaf(kv.w, q2.w, 1.f)), a2);
        float4 q3 = *(const float4*)(qb + 3 * Uu + 4 * i);
        a3 = fmaf(w4.x, fast_rcp(fmaf(kv.x, q3.x, 1.f)), a3);
        a3 = fmaf(w4.y, fast_rcp(fmaf(kv.y, q3.y, 1.f)), a3);
        a3 = fmaf(w4.z, fast_rcp(fmaf(kv.z, q3.z, 1.f)), a3);
        a3 = fmaf(w4.w, fast_rcp(fmaf(kv.w, q3.w, 1.f)), a3);
    }

    const float M2L = -2.8853900817779268f;  // -2*log2(e)
    float* o = sa + t * PAD + sq0;
    o[0] = fast_ex2(fmaf(M2L, a0, swl));
    o[1] = fast_ex2(fmaf(M2L, a1, swl));
    o[2] = fast_ex2(fmaf(M2L, a2, swl));
    o[3] = fast_ex2(fmaf(M2L, a3, swl));
}

// ---------------------------------------------------------------------------
// Phase C (one chunk, 32 t-steps): thread owns a d-pair, all 16 s.
// ---------------------------------------------------------------------------
__device__ __forceinline__ void phaseC(unsigned long long* __restrict__ acc,
                                       const float* __restrict__ sa,
                                       const float* __restrict__ xb, int t0) {
#pragma unroll 4
    for (int t = t0; t < t0 + 32; t++) {
        float2 xv = *(const float2*)(xb + (size_t)t * Dd);  // coalesced LDG.64
        unsigned long long xx0 = pack2(xv.x, xv.x);
        unsigned long long xx1 = pack2(xv.y, xv.y);

        const float* r = sa + t * PAD;
        ulonglong2 p0 = *(const ulonglong2*)(r);       // broadcast LDS.128
        ulonglong2 p1 = *(const ulonglong2*)(r + 4);
        ulonglong2 p2 = *(const ulonglong2*)(r + 8);
        ulonglong2 p3 = *(const ulonglong2*)(r + 12);

        fma2(acc[0],  p0.x, xx0); fma2(acc[1],  p0.x, xx1);
        fma2(acc[2],  p0.y, xx0); fma2(acc[3],  p0.y, xx1);
        fma2(acc[4],  p1.x, xx0); fma2(acc[5],  p1.x, xx1);
        fma2(acc[6],  p1.y, xx0); fma2(acc[7],  p1.y, xx1);
        fma2(acc[8],  p2.x, xx0); fma2(acc[9],  p2.x, xx1);
        fma2(acc[10], p2.y, xx0); fma2(acc[11], p2.y, xx1);
        fma2(acc[12], p3.x, xx0); fma2(acc[13], p3.x, xx1);
        fma2(acc[14], p3.y, xx0); fma2(acc[15], p3.y, xx1);
    }
}

// ---------------------------------------------------------------------------
// Kernel 2 (fused + software-pipelined), 512 threads, grid = 256:
//   segments: A(0) | A(1)+C(0) | A(2)+C(1) | A(3)+C(2) | C(3)+B' | epilogue
//   No-max softmax: w = exp(alpha) stored directly (alpha bounded by sum|Wa|);
//   normalization folded into epilogue via sinv[s].
// ---------------------------------------------------------------------------
__global__ __launch_bounds__(512, 2) void attn_kernel(const float* __restrict__ x,
                                                      const float* __restrict__ Wa,
                                                      float* __restrict__ out) {
    __shared__ __align__(16) float sa[Ll * PAD];  // 40 KB: w tile [t][s] / reduce buf
    __shared__ __align__(16) float sq[TS * Uu];   // 2 KB
    __shared__ float swa[Uu];
    __shared__ float sinv[TS];

    const int tid = threadIdx.x;
    const int b = blockIdx.x >> 5;
    const int s0 = (blockIdx.x & 31) * TS;

    sq[tid] = g_q[((size_t)b * Ll + s0) * Uu + tid];  // 512 = TS*Uu exactly
    if (tid < Uu) swa[tid] = Wa[tid];
    __syncthreads();

    float sumwa = 0.f;
#pragma unroll
    for (int u = 0; u < Uu; u++) sumwa += swa[u];
    const float swl = sumwa * 1.4426950408889634f;  // sumwa * log2(e)

    // A-role: t = chunk*128 + (tid&127), s-quarter = (tid>>7)*4
    const int tA = tid & 127;
    const int sq0 = (tid >> 7) * 4;
    const float* gkb = g_k + (size_t)b * Ll * Uu;
    const float4* swa4 = (const float4*)swa;

    // C-role: d-pair dp = tid&127, t-subrange tq = tid>>7 (32 t per chunk)
    const int dp = tid & 127;
    const int tq = tid >> 7;
    const int d = dp * 2;
    const float* __restrict__ xb = x + (size_t)b * Ll * Dd + d;

    unsigned long long acc[16];
#pragma unroll
    for (int j = 0; j < 16; j++) acc[j] = 0ull;

    // ---- pipelined segments (A(c) fills chunk c; C(c) consumes it) ----
    phaseA(sa, sq, swa4, gkb, 0 * 128 + tA, sq0, swl);
    __syncthreads();
    phaseA(sa, sq, swa4, gkb, 1 * 128 + tA, sq0, swl);
    phaseC(acc, sa, xb, 0 * 128 + tq * 32);
    __syncthreads();
    phaseA(sa, sq, swa4, gkb, 2 * 128 + tA, sq0, swl);
    phaseC(acc, sa, xb, 1 * 128 + tq * 32);
    __syncthreads();
    phaseA(sa, sq, swa4, gkb, 3 * 128 + tA, sq0, swl);
    phaseC(acc, sa, xb, 2 * 128 + tq * 32);
    __syncthreads();
    phaseC(acc, sa, xb, 3 * 128 + tq * 32);

    // ---- B': row sums -> sinv (runs alongside last C; sa is read-only here)
    {
        const int w = tid >> 5;       // 16 warps, one s-row each
        const int lane = tid & 31;
        float ss = 0.f;
#pragma unroll
        for (int i = 0; i < 16; i++) ss += sa[(lane + 32 * i) * PAD + w];
#pragma unroll
        for (int off = 16; off > 0; off >>= 1)
            ss += __shfl_xor_sync(0xffffffffu, ss, off);
        if (lane == 0) sinv[w] = fast_rcp(ss);
    }
    __syncthreads();  // sa now reusable; sinv visible

    // ---- tree-reduce the 4 t-quarters, scale by sinv, store ----
    {
        unsigned long long* red = (unsigned long long*)sa;

        if (tq & 1) {
            unsigned long long* dst = red + ((tq >> 1) * 128 + dp) * RSTRIDE;
#pragma unroll
            for (int j = 0; j < 16; j++) dst[j] = acc[j];
        }
        __syncthreads();
        if (!(tq & 1)) {
            const unsigned long long* src = red + ((tq >> 1) * 128 + dp) * RSTRIDE;
#pragma unroll
            for (int j = 0; j < 16; j++) add2(acc[j], src[j]);
        }
        __syncthreads();

        if (tq == 2) {
            unsigned long long* dst = red + dp * RSTRIDE;
#pragma unroll
            for (int j = 0; j < 16; j++) dst[j] = acc[j];
        }
        __syncthreads();
        if (tq == 0) {
            const unsigned long long* src = red + dp * RSTRIDE;
#pragma unroll
            for (int j = 0; j < 16; j++) add2(acc[j], src[j]);

            float* ob = out + ((size_t)b * Ll + s0) * Dd + d;
#pragma unroll
            for (int jp = 0; jp < 8; jp++) {
                unsigned long long sc = pack2(sinv[2 * jp], sinv[2 * jp + 1]);
                mul2(acc[2 * jp + 0], sc);
                mul2(acc[2 * jp + 1], sc);
                float lo0, hi0, lo1, hi1;
                unpack2(lo0, hi0, acc[2 * jp + 0]);  // col d  : s=2jp, 2jp+1
                unpack2(lo1, hi1, acc[2 * jp + 1]);  // col d+1
                *(float2*)(ob + (2 * jp + 0) * Dd) = make_float2(lo0, lo1);
                *(float2*)(ob + (2 * jp + 1) * Dd) = make_float2(hi0, hi1);
            }
        }
    }
}

// ---------------------------------------------------------------------------
extern "C" void kernel_launch(void* const* d_in, const int* in_sizes, int n_in,
                              void* d_out, int out_size) {
    const float* x  = (const float*)d_in[0];
    const float* Wt = (const float*)d_in[1];
    const float* Wx = (const float*)d_in[2];
    const float* bh = (const float*)d_in[3];
    const float* Wa = (const float*)d_in[4];
    // d_in[5] = ba: uniform shift of alpha -> softmax-invariant, exactly droppable
    float* out = (float*)d_out;

    qk_kernel<<<Bb * Ll / 8, 256>>>(x, Wt, Wx, bh);
    attn_kernel<<<Bb * (Ll / TS), 512>>>(x, Wa, out);
}